// round 16
// baseline (speedup 1.0000x reference)
#include <cuda_runtime.h>
#include <cuda_bf16.h>
#include <cstdint>

#define DIMV    64
#define KSPLIT  8
#define KS_PER_CTA 80         // 640 padded K-steps / KSPLIT
#define NKP 640

// B packed as uint4, fragment order under the K-permutation that makes A loads
// float4-contiguous. ks in [625,640) zero-filled by pack_kernel each launch.
__device__ uint4 g_Bp[NKP * 4 * 32];
__device__ float g_w[10240];     // per-row interaction scalar (zeroed by pack_kernel)
__device__ int   g_cnt[768];     // per-tile split-K arrival counter (zeroed by pack_kernel)

// ---------------- helpers ----------------
__device__ __forceinline__ uint32_t cvt_bf16x2(float lo, float hi) {
    uint32_t r;
    asm("cvt.rn.bf16x2.f32 %0, %1, %2;" : "=r"(r) : "f"(hi), "f"(lo));
    return r;
}
__device__ __forceinline__ void mma16816(float c[4], const uint32_t a[4],
                                         uint32_t b0, uint32_t b1) {
    asm volatile(
        "mma.sync.aligned.m16n8k16.row.col.f32.bf16.bf16.f32 "
        "{%0,%1,%2,%3}, {%4,%5,%6,%7}, {%8,%9}, {%0,%1,%2,%3};"
        : "+f"(c[0]), "+f"(c[1]), "+f"(c[2]), "+f"(c[3])
        : "r"(a[0]), "r"(a[1]), "r"(a[2]), "r"(a[3]), "r"(b0), "r"(b1));
}

// ---------------- kernel 1: pack x -> Bp (smem-free, 1 warp per task) --------
// warpid = ks*4 + jj ; 2560 warps = 320 blocks x 8 warps.
// ks in [625,640) writes zeros. Blocks 0..39 zero g_w; blocks 40..42 zero g_cnt.
__global__ void __launch_bounds__(256) pack_kernel(const float* __restrict__ x, int N) {
    if (blockIdx.x < 40) {
        g_w[blockIdx.x * 256 + threadIdx.x] = 0.0f;
    } else if (blockIdx.x < 43) {
        g_cnt[(blockIdx.x - 40) * 256 + threadIdx.x] = 0;
    }

    int warpid = blockIdx.x * 8 + (threadIdx.x >> 5);
    int lane = threadIdx.x & 31;
    int ks = warpid >> 2, jj = warpid & 3;
    if (ks >= NKP) return;

    int g = lane >> 2, t = lane & 3;
    int n0 = jj * 16 + g, n1 = n0 + 8;
    int k0 = ks * 16 + 4 * t;

    uint4 v = make_uint4(0u, 0u, 0u, 0u);
    if (ks * 16 < N) {
        const float* p0 = x + (size_t)k0 * DIMV;
        float a0 = __ldg(p0 + n0),            a1 = __ldg(p0 + DIMV + n0);
        float a2 = __ldg(p0 + 2 * DIMV + n0), a3 = __ldg(p0 + 3 * DIMV + n0);
        float b0 = __ldg(p0 + n1),            b1 = __ldg(p0 + DIMV + n1);
        float b2 = __ldg(p0 + 2 * DIMV + n1), b3 = __ldg(p0 + 3 * DIMV + n1);
        v.x = cvt_bf16x2(a0, a1);
        v.y = cvt_bf16x2(a2, a3);
        v.z = cvt_bf16x2(b0, b1);
        v.w = cvt_bf16x2(b2, b3);
    }
    g_Bp[(size_t)(ks * 4 + jj) * 32 + lane] = v;
}

// ---------------- kernel 2: direct-LDG GEMM, split-K x8, fused finish --------
__global__ void __launch_bounds__(256, 2)
gemm_kernel(const float* __restrict__ A, const float* __restrict__ x,
            float* __restrict__ out, int N) {
    __shared__ float wred[8][16];
    __shared__ int lastflag;

    int tid = threadIdx.x, w = tid >> 5, lane = tid & 31;
    int g = lane >> 2, t = lane & 3;
    int tile  = blockIdx.x >> 3;
    int kpart = blockIdx.x & 7;
    int row0 = tile * 16;
    int r0 = row0 + g, r1 = r0 + 8;

    const float* rowA0 = A + (size_t)r0 * N + 4 * t;
    const float* rowA1 = A + (size_t)r1 * N + 4 * t;
    const uint4* pB = g_Bp + lane;

    float c[8][4];
#pragma unroll
    for (int j = 0; j < 8; j++)
#pragma unroll
        for (int q = 0; q < 4; q++) c[j][q] = 0.0f;

    int ksbase = kpart * KS_PER_CTA + w;

#pragma unroll 5
    for (int i = 0; i < KS_PER_CTA / 8; i++) {     // 10 iterations
        int ks = ksbase + 8 * i;
        int gk = ks * 16;
        if (gk >= N) gk = 0;                        // pad K-step: B == 0

        float4 va = *(const float4*)(rowA0 + gk);
        float4 vb = *(const float4*)(rowA1 + gk);

        uint4 bb[4];
#pragma unroll
        for (int jj = 0; jj < 4; jj++)
            bb[jj] = pB[(size_t)(ks * 4 + jj) * 32];

        uint32_t ar[4];
        ar[0] = cvt_bf16x2(va.x, va.y);
        ar[1] = cvt_bf16x2(vb.x, vb.y);
        ar[2] = cvt_bf16x2(va.z, va.w);
        ar[3] = cvt_bf16x2(vb.z, vb.w);

#pragma unroll
        for (int jj = 0; jj < 4; jj++) {
            mma16816(c[2 * jj],     ar, bb[jj].x, bb[jj].y);
            mma16816(c[2 * jj + 1], ar, bb[jj].z, bb[jj].w);
        }
    }

    // ---- epilogue: partial dot x . (Ax)_partial, cross-warp reduce ----
    float s0 = 0.0f, s1 = 0.0f;
#pragma unroll
    for (int j = 0; j < 8; j++) {
        int col = j * 8 + t * 2;
        float2 x0 = *(const float2*)(x + (size_t)r0 * DIMV + col);
        float2 x1 = *(const float2*)(x + (size_t)r1 * DIMV + col);
        s0 += x0.x * c[j][0] + x0.y * c[j][1];
        s1 += x1.x * c[j][2] + x1.y * c[j][3];
    }
    s0 += __shfl_xor_sync(0xFFFFFFFFu, s0, 1);
    s0 += __shfl_xor_sync(0xFFFFFFFFu, s0, 2);
    s1 += __shfl_xor_sync(0xFFFFFFFFu, s1, 1);
    s1 += __shfl_xor_sync(0xFFFFFFFFu, s1, 2);

    if (t == 0) { wred[w][g] = s0; wred[w][g + 8] = s1; }
    __syncthreads();

    if (tid < 16) {
        float acc = 0.0f;
#pragma unroll
        for (int q = 0; q < 8; q++) acc += wred[q][tid];
        atomicAdd(&g_w[row0 + tid], acc);
    }
    __syncthreads();
    if (tid == 0) {
        __threadfence();
        int old = atomicAdd(&g_cnt[tile], 1);
        lastflag = (old == KSPLIT - 1);
    }
    __syncthreads();

    // last-arriving CTA of this tile writes the final 16x64 output tile
    if (lastflag) {
        int r = tid >> 4, cq = tid & 15;
        int grow = row0 + r;
        float inter = 0.01f * __ldcg(&g_w[grow]);
        float4 xv = *(const float4*)(x + (size_t)grow * DIMV + cq * 4);
        float4 o;
        o.x = 1.0f - 0.1f * xv.x - inter;
        o.y = 1.0f - 0.1f * xv.y - inter;
        o.z = 1.0f - 0.1f * xv.z - inter;
        o.w = 1.0f - 0.1f * xv.w - inter;
        *(float4*)(out + (size_t)grow * DIMV + cq * 4) = o;
    }
}

// ---------------- launch ----------------
extern "C" void kernel_launch(void* const* d_in, const int* in_sizes, int n_in,
                              void* d_out, int out_size) {
    const float* x = (const float*)d_in[1];
    const float* A = (const float*)d_in[2];
    float* out = (float*)d_out;
    int N = in_sizes[1] / DIMV;   // 10000

    pack_kernel<<<320, 256>>>(x, N);   // also zeroes g_w and g_cnt

    gemm_kernel<<<(N / 16) * KSPLIT, 256>>>(A, x, out, N);
}

// round 17
// speedup vs baseline: 1.1551x; 1.1551x over previous
#include <cuda_runtime.h>
#include <cuda_bf16.h>
#include <cstdint>

#define DIMV    64
#define KSPLIT  8
#define KS_PER_CTA 80         // 640 padded K-steps / KSPLIT
#define NKP 640

// B packed as uint4, fragment order under the K-permutation that makes A loads
// float4-contiguous. ks in [625,640) zero-filled by pack_kernel each launch.
__device__ uint4 g_Bp[NKP * 4 * 32];
__device__ float g_w[10240];     // per-row interaction scalar (zeroed by pack_kernel)

// ---------------- helpers ----------------
__device__ __forceinline__ uint32_t cvt_bf16x2(float lo, float hi) {
    uint32_t r;
    asm("cvt.rn.bf16x2.f32 %0, %1, %2;" : "=r"(r) : "f"(hi), "f"(lo));
    return r;
}
__device__ __forceinline__ float4 ldcs128(const float* p) {
    float4 v;
    asm volatile("ld.global.cs.v4.f32 {%0,%1,%2,%3}, [%4];"
                 : "=f"(v.x), "=f"(v.y), "=f"(v.z), "=f"(v.w) : "l"(p));
    return v;
}
__device__ __forceinline__ void mma16816(float c[4], const uint32_t a[4],
                                         uint32_t b0, uint32_t b1) {
    asm volatile(
        "mma.sync.aligned.m16n8k16.row.col.f32.bf16.bf16.f32 "
        "{%0,%1,%2,%3}, {%4,%5,%6,%7}, {%8,%9}, {%0,%1,%2,%3};"
        : "+f"(c[0]), "+f"(c[1]), "+f"(c[2]), "+f"(c[3])
        : "r"(a[0]), "r"(a[1]), "r"(a[2]), "r"(a[3]), "r"(b0), "r"(b1));
}

// ---------------- kernel 1: pack x -> Bp (smem-free, 1 warp per task) --------
// warpid = ks*4 + jj ; 2560 warps = 320 blocks x 8 warps.
// ks in [625,640) writes zeros. Blocks 0..39 also zero g_w (40*256 = 10240).
__global__ void __launch_bounds__(256) pack_kernel(const float* __restrict__ x, int N) {
    if (blockIdx.x < 40) g_w[blockIdx.x * 256 + threadIdx.x] = 0.0f;

    int warpid = blockIdx.x * 8 + (threadIdx.x >> 5);
    int lane = threadIdx.x & 31;
    int ks = warpid >> 2, jj = warpid & 3;
    if (ks >= NKP) return;

    int g = lane >> 2, t = lane & 3;
    int n0 = jj * 16 + g, n1 = n0 + 8;
    int k0 = ks * 16 + 4 * t;

    uint4 v = make_uint4(0u, 0u, 0u, 0u);
    if (ks * 16 < N) {
        const float* p0 = x + (size_t)k0 * DIMV;
        float a0 = __ldg(p0 + n0),            a1 = __ldg(p0 + DIMV + n0);
        float a2 = __ldg(p0 + 2 * DIMV + n0), a3 = __ldg(p0 + 3 * DIMV + n0);
        float b0 = __ldg(p0 + n1),            b1 = __ldg(p0 + DIMV + n1);
        float b2 = __ldg(p0 + 2 * DIMV + n1), b3 = __ldg(p0 + 3 * DIMV + n1);
        v.x = cvt_bf16x2(a0, a1);
        v.y = cvt_bf16x2(a2, a3);
        v.z = cvt_bf16x2(b0, b1);
        v.w = cvt_bf16x2(b2, b3);
    }
    g_Bp[(size_t)(ks * 4 + jj) * 32 + lane] = v;
}

// ---------------- kernel 2: direct-LDG GEMM, split-K x8, streaming A ---------
// CTA = (tile 16 rows, kpart). 8 warps stride the CTA's 80 K-steps.
__global__ void __launch_bounds__(256, 2)
gemm_kernel(const float* __restrict__ A, const float* __restrict__ x, int N) {
    __shared__ float wred[8][16];

    int tid = threadIdx.x, w = tid >> 5, lane = tid & 31;
    int g = lane >> 2, t = lane & 3;
    int tile  = blockIdx.x >> 3;
    int kpart = blockIdx.x & 7;
    int row0 = tile * 16;
    int r0 = row0 + g, r1 = r0 + 8;

    const float* rowA0 = A + (size_t)r0 * N + 4 * t;
    const float* rowA1 = A + (size_t)r1 * N + 4 * t;
    const uint4* pB = g_Bp + lane;

    float c[8][4];
#pragma unroll
    for (int j = 0; j < 8; j++)
#pragma unroll
        for (int q = 0; q < 4; q++) c[j][q] = 0.0f;

    int ksbase = kpart * KS_PER_CTA + w;

#pragma unroll 5
    for (int i = 0; i < KS_PER_CTA / 8; i++) {     // 10 iterations
        int ks = ksbase + 8 * i;
        int gk = ks * 16;
        if (gk >= N) gk = 0;                        // pad K-step: B == 0

        float4 va = ldcs128(rowA0 + gk);            // streaming: no L2 residency
        float4 vb = ldcs128(rowA1 + gk);

        uint4 bb[4];
#pragma unroll
        for (int jj = 0; jj < 4; jj++)
            bb[jj] = __ldg(&pB[(size_t)(ks * 4 + jj) * 32]);

        uint32_t ar[4];
        ar[0] = cvt_bf16x2(va.x, va.y);
        ar[1] = cvt_bf16x2(vb.x, vb.y);
        ar[2] = cvt_bf16x2(va.z, va.w);
        ar[3] = cvt_bf16x2(vb.z, vb.w);

#pragma unroll
        for (int jj = 0; jj < 4; jj++) {
            mma16816(c[2 * jj],     ar, bb[jj].x, bb[jj].y);
            mma16816(c[2 * jj + 1], ar, bb[jj].z, bb[jj].w);
        }
    }

    // ---- epilogue: partial dot x . (Ax)_partial, cross-warp reduce ----
    float s0 = 0.0f, s1 = 0.0f;
#pragma unroll
    for (int j = 0; j < 8; j++) {
        int col = j * 8 + t * 2;
        float2 x0 = *(const float2*)(x + (size_t)r0 * DIMV + col);
        float2 x1 = *(const float2*)(x + (size_t)r1 * DIMV + col);
        s0 += x0.x * c[j][0] + x0.y * c[j][1];
        s1 += x1.x * c[j][2] + x1.y * c[j][3];
    }
    s0 += __shfl_xor_sync(0xFFFFFFFFu, s0, 1);
    s0 += __shfl_xor_sync(0xFFFFFFFFu, s0, 2);
    s1 += __shfl_xor_sync(0xFFFFFFFFu, s1, 1);
    s1 += __shfl_xor_sync(0xFFFFFFFFu, s1, 2);

    if (t == 0) { wred[w][g] = s0; wred[w][g + 8] = s1; }
    __syncthreads();

    if (tid < 16) {
        float acc = 0.0f;
#pragma unroll
        for (int q = 0; q < 8; q++) acc += wred[q][tid];
        atomicAdd(&g_w[row0 + tid], acc);
    }
}

// ---------------- kernel 3: elementwise finish ----------------
__global__ void __launch_bounds__(256) final_kernel(const float* __restrict__ x,
                                                    float* __restrict__ out) {
    int i = blockIdx.x * 256 + threadIdx.x;   // one float4 per thread
    int r = i >> 4, cq = i & 15;
    float inter = 0.01f * g_w[r];
    float4 xv = *(const float4*)(x + (size_t)r * DIMV + cq * 4);
    float4 o;
    o.x = 1.0f - 0.1f * xv.x - inter;
    o.y = 1.0f - 0.1f * xv.y - inter;
    o.z = 1.0f - 0.1f * xv.z - inter;
    o.w = 1.0f - 0.1f * xv.w - inter;
    *(float4*)(out + (size_t)r * DIMV + cq * 4) = o;
}

// ---------------- launch ----------------
extern "C" void kernel_launch(void* const* d_in, const int* in_sizes, int n_in,
                              void* d_out, int out_size) {
    const float* x = (const float*)d_in[1];
    const float* A = (const float*)d_in[2];
    float* out = (float*)d_out;
    int N = in_sizes[1] / DIMV;   // 10000

    pack_kernel<<<320, 256>>>(x, N);   // also zeroes g_w

    gemm_kernel<<<(N / 16) * KSPLIT, 256>>>(A, x, N);

    final_kernel<<<(N * DIMV) / (256 * 4), 256>>>(x, out);
}